// round 2
// baseline (speedup 1.0000x reference)
#include <cuda_runtime.h>
#include <math.h>

#define T_LEN 4096
#define H_DIM 1024
#define NCOL  6144   // 2 dirs * 3 gates * H

// Scratch (allocation-free rule: __device__ globals)
static __device__ float g_xproj[(size_t)T_LEN * NCOL];   // ~100.7 MB
static __device__ float g_h[2][2][H_DIM];                // [buf parity][dir][j]
static __device__ int   g_flags[128];                    // steps completed per block

// ---------------------------------------------------------------------------
// Kernel 1: x_proj[t, d*3072+g] = sum_h emb[x[t],h] * w_ih[d,g,h] + b_ih[d,g]
// Classic fp32 SGEMM 128x128x16, fused embedding gather on the A side.
// ---------------------------------------------------------------------------
__global__ void __launch_bounds__(256) gemm_xproj_kernel(
    const int*   __restrict__ x,
    const float* __restrict__ emb,
    const float* __restrict__ w,      // (6144, 1024) row-major
    const float* __restrict__ bias)   // (6144)
{
    __shared__ float As[16][132];
    __shared__ float Bs[16][132];

    const int tid = threadIdx.x;
    const int m0 = blockIdx.y * 128;
    const int n0 = blockIdx.x * 128;

    const int r0 = tid >> 2;      // 0..63
    const int c4 = tid & 3;       // 0..3

    const float* arow0 = emb + (size_t)__ldg(x + m0 + r0)      * H_DIM + c4 * 4;
    const float* arow1 = emb + (size_t)__ldg(x + m0 + r0 + 64) * H_DIM + c4 * 4;
    const float* brow0 = w + (size_t)(n0 + r0)      * H_DIM + c4 * 4;
    const float* brow1 = w + (size_t)(n0 + r0 + 64) * H_DIM + c4 * 4;

    const int tx = tid & 15;
    const int ty = tid >> 4;

    float acc[8][8] = {};

    for (int k0 = 0; k0 < H_DIM; k0 += 16) {
        float4 a0 = *(const float4*)(arow0 + k0);
        float4 a1 = *(const float4*)(arow1 + k0);
        float4 b0 = *(const float4*)(brow0 + k0);
        float4 b1 = *(const float4*)(brow1 + k0);
        __syncthreads();
        As[c4*4+0][r0]    = a0.x; As[c4*4+1][r0]    = a0.y;
        As[c4*4+2][r0]    = a0.z; As[c4*4+3][r0]    = a0.w;
        As[c4*4+0][r0+64] = a1.x; As[c4*4+1][r0+64] = a1.y;
        As[c4*4+2][r0+64] = a1.z; As[c4*4+3][r0+64] = a1.w;
        Bs[c4*4+0][r0]    = b0.x; Bs[c4*4+1][r0]    = b0.y;
        Bs[c4*4+2][r0]    = b0.z; Bs[c4*4+3][r0]    = b0.w;
        Bs[c4*4+0][r0+64] = b1.x; Bs[c4*4+1][r0+64] = b1.y;
        Bs[c4*4+2][r0+64] = b1.z; Bs[c4*4+3][r0+64] = b1.w;
        __syncthreads();
        #pragma unroll
        for (int k = 0; k < 16; ++k) {
            float a[8], b[8];
            *(float4*)(a + 0) = *(const float4*)&As[k][ty * 8];
            *(float4*)(a + 4) = *(const float4*)&As[k][ty * 8 + 4];
            *(float4*)(b + 0) = *(const float4*)&Bs[k][tx * 8];
            *(float4*)(b + 4) = *(const float4*)&Bs[k][tx * 8 + 4];
            #pragma unroll
            for (int i = 0; i < 8; ++i)
                #pragma unroll
                for (int j = 0; j < 8; ++j)
                    acc[i][j] = fmaf(a[i], b[j], acc[i][j]);
        }
    }

    float4 bias0 = *(const float4*)(bias + n0 + tx * 8);
    float4 bias1 = *(const float4*)(bias + n0 + tx * 8 + 4);
    #pragma unroll
    for (int i = 0; i < 8; ++i) {
        float* crow = g_xproj + (size_t)(m0 + ty * 8 + i) * NCOL + n0 + tx * 8;
        float4 v0 = make_float4(acc[i][0] + bias0.x, acc[i][1] + bias0.y,
                                acc[i][2] + bias0.z, acc[i][3] + bias0.w);
        float4 v1 = make_float4(acc[i][4] + bias1.x, acc[i][5] + bias1.y,
                                acc[i][6] + bias1.z, acc[i][7] + bias1.w);
        *(float4*)(crow)     = v0;
        *(float4*)(crow + 4) = v1;
    }
}

// ---------------------------------------------------------------------------
// Kernel 2: persistent GRU scan. 128 blocks (all co-resident), 512 threads.
// Block b: dir d = b>>6, units j = (b&63)*16 .. +15, one unit per warp.
// W_hh rows for the 48 dots live in registers (96 floats / lane).
// Cross-block sync: per-block step flags in global, double-buffered h.
// ---------------------------------------------------------------------------
__global__ void __launch_bounds__(512, 1) gru_scan_kernel(
    const float* __restrict__ w_hh,   // (6144, 1024) flat: [d][gate*1024+j][h]
    const float* __restrict__ b_hh,   // (6144)
    float* __restrict__ out)          // [t][d*1024+j] then hidden appended later
{
    __shared__ float hsm[H_DIM];
    __shared__ float hnew_sm[16];

    const int tid   = threadIdx.x;
    const int lane  = tid & 31;
    const int wrp   = tid >> 5;            // 0..15
    const int blk   = blockIdx.x;          // 0..127
    const int d     = blk >> 6;            // 0 or 1
    const int jbase = (blk & 63) * 16;
    const int j     = jbase + wrp;         // 0..1023

    const size_t rr = (size_t)(d * 3072 + j) * H_DIM;
    const size_t rz = rr + (size_t)1024 * H_DIM;
    const size_t rn = rz + (size_t)1024 * H_DIM;

    // Weight preload: lane covers h indices {i*128 + lane*4 + k}
    float4 wr[8], wz[8], wn[8];
    {
        const float4* pr = (const float4*)(w_hh + rr);
        const float4* pz = (const float4*)(w_hh + rz);
        const float4* pn = (const float4*)(w_hh + rn);
        #pragma unroll
        for (int i = 0; i < 8; ++i) {
            wr[i] = pr[i * 32 + lane];
            wz[i] = pz[i * 32 + lane];
            wn[i] = pn[i * 32 + lane];
        }
    }
    float bhr = 0.f, bhz = 0.f, bhn = 0.f;
    if (lane == 0) {
        bhr = __ldg(b_hh + d * 3072 + j);
        bhz = __ldg(b_hh + d * 3072 + 1024 + j);
        bhn = __ldg(b_hh + d * 3072 + 2048 + j);
    }

    const float* xp = g_xproj + d * 3072 + j;

    for (int s = 0; s < T_LEN; ++s) {
        // Prefetch x-gate inputs (independent of h; hides DRAM latency)
        float xr = 0.f, xz = 0.f, xn = 0.f;
        if (lane == 0) {
            const float* p = xp + (size_t)s * NCOL;
            xr = __ldg(p);
            xz = __ldg(p + 1024);
            xn = __ldg(p + 2048);
        }

        // Wait until all producers of this direction finished step s-1
        if (tid < 64) {
            volatile int* f = g_flags + (d << 6) + tid;
            while (*f < s) { }
        }
        __syncthreads();

        // Stage h_s into smem (L2-coherent loads; L1 may be stale cross-SM)
        if (tid < 256) {
            const float4* hb = (const float4*)(&g_h[s & 1][d][0]);
            ((float4*)hsm)[tid] = __ldcg(hb + tid);
        }
        __syncthreads();

        // 3 dot products of length 1024, partitioned across 32 lanes
        float ar = 0.f, az = 0.f, an = 0.f;
        #pragma unroll
        for (int i = 0; i < 8; ++i) {
            float4 hv = ((const float4*)hsm)[i * 32 + lane];
            ar = fmaf(wr[i].x, hv.x, ar); ar = fmaf(wr[i].y, hv.y, ar);
            ar = fmaf(wr[i].z, hv.z, ar); ar = fmaf(wr[i].w, hv.w, ar);
            az = fmaf(wz[i].x, hv.x, az); az = fmaf(wz[i].y, hv.y, az);
            az = fmaf(wz[i].z, hv.z, az); az = fmaf(wz[i].w, hv.w, az);
            an = fmaf(wn[i].x, hv.x, an); an = fmaf(wn[i].y, hv.y, an);
            an = fmaf(wn[i].z, hv.z, an); an = fmaf(wn[i].w, hv.w, an);
        }
        #pragma unroll
        for (int o = 16; o > 0; o >>= 1) {
            ar += __shfl_xor_sync(0xffffffffu, ar, o);
            az += __shfl_xor_sync(0xffffffffu, az, o);
            an += __shfl_xor_sync(0xffffffffu, an, o);
        }

        if (lane == 0) {
            float r = 1.f / (1.f + __expf(-(xr + ar + bhr)));
            float z = 1.f / (1.f + __expf(-(xz + az + bhz)));
            float n = tanhf(xn + r * (an + bhn));
            float hprev = hsm[j];
            hnew_sm[wrp] = (1.f - z) * n + z * hprev;
        }
        __syncthreads();

        // Publish: outputs row + next-step h slice + release flag
        if (tid < 16)
            out[(size_t)s * 2048 + d * 1024 + jbase + tid] = hnew_sm[tid];
        if (tid == 0) {
            float4*       dst = (float4*)(&g_h[(s + 1) & 1][d][jbase]);
            const float4* src = (const float4*)hnew_sm;
            dst[0] = src[0]; dst[1] = src[1]; dst[2] = src[2]; dst[3] = src[3];
            __threadfence();
            ((volatile int*)g_flags)[blk] = s + 1;
        }
    }
}

// ---------------------------------------------------------------------------
// Kernel 3: hidden = h_T[dir0] + h_T[dir1]  (final state lives in buffer 0)
// ---------------------------------------------------------------------------
__global__ void hidden_kernel(float* __restrict__ out)
{
    int j = threadIdx.x;
    out[(size_t)T_LEN * 2048 + j] = g_h[0][0][j] + g_h[0][1][j];
}

// ---------------------------------------------------------------------------
extern "C" void kernel_launch(void* const* d_in, const int* in_sizes, int n_in,
                              void* d_out, int out_size)
{
    const int*   x    = (const int*)d_in[0];
    const float* emb  = (const float*)d_in[1];
    const float* w_ih = (const float*)d_in[2];
    const float* w_hh = (const float*)d_in[3];
    const float* b_ih = (const float*)d_in[4];
    const float* b_hh = (const float*)d_in[5];
    float* out = (float*)d_out;

    void* pflags = nullptr;
    void* ph     = nullptr;
    cudaGetSymbolAddress(&pflags, g_flags);
    cudaGetSymbolAddress(&ph,     g_h);
    cudaMemsetAsync(pflags, 0, sizeof(int) * 128, 0);
    cudaMemsetAsync(ph,     0, sizeof(float) * 2 * 2 * H_DIM, 0);

    gemm_xproj_kernel<<<dim3(NCOL / 128, T_LEN / 128), 256>>>(x, emb, w_ih, b_ih);
    gru_scan_kernel<<<128, 512>>>(w_hh, b_hh, out);
    hidden_kernel<<<1, H_DIM>>>(out);
}

// round 9
// speedup vs baseline: 1.0575x; 1.0575x over previous
#include <cuda_runtime.h>
#include <math.h>

#define T_LEN 4096
#define H_DIM 1024
#define NCOL  6144   // 2 dirs * 3 gates * H

// Scratch (allocation-free rule: __device__ globals)
static __device__ float g_xproj[(size_t)T_LEN * NCOL];   // ~100.7 MB
static __device__ float g_h[2][2][H_DIM];                // [buf parity][dir][j]
static __device__ int   g_flags[128];                    // steps completed per block

// ---- packed f32x2 helpers (pure arithmetic; sync protocol untouched) ------
__device__ __forceinline__ void ffma2(unsigned long long &d,
                                      unsigned long long a,
                                      unsigned long long b) {
    asm("fma.rn.f32x2 %0, %1, %2, %0;" : "+l"(d) : "l"(a), "l"(b));
}
__device__ __forceinline__ unsigned long long pack2(float lo, float hi) {
    unsigned long long r;
    asm("mov.b64 %0, {%1, %2};" : "=l"(r) : "f"(lo), "f"(hi));
    return r;
}
__device__ __forceinline__ void unpack2(unsigned long long v, float &lo, float &hi) {
    asm("mov.b64 {%0, %1}, %2;" : "=f"(lo), "=f"(hi) : "l"(v));
}

// ---------------------------------------------------------------------------
// Kernel 1: x_proj = emb[x] @ w_ih^T + b_ih. 128x128x16 SGEMM, FFMA2 inner.
// ---------------------------------------------------------------------------
__global__ void __launch_bounds__(256) gemm_xproj_kernel(
    const int*   __restrict__ x,
    const float* __restrict__ emb,
    const float* __restrict__ w,      // (6144, 1024) row-major
    const float* __restrict__ bias)   // (6144)
{
    __shared__ float As[16][132];
    __shared__ float Bs[16][132];

    const int tid = threadIdx.x;
    const int m0 = blockIdx.y * 128;
    const int n0 = blockIdx.x * 128;

    const int r0 = tid >> 2;      // 0..63
    const int c4 = tid & 3;       // 0..3

    const float* arow0 = emb + (size_t)__ldg(x + m0 + r0)      * H_DIM + c4 * 4;
    const float* arow1 = emb + (size_t)__ldg(x + m0 + r0 + 64) * H_DIM + c4 * 4;
    const float* brow0 = w + (size_t)(n0 + r0)      * H_DIM + c4 * 4;
    const float* brow1 = w + (size_t)(n0 + r0 + 64) * H_DIM + c4 * 4;

    const int tx = tid & 15;
    const int ty = tid >> 4;

    // acc2[i][jj] = (acc[i][2jj], acc[i][2jj+1]) packed f32x2
    unsigned long long acc2[8][4];
    #pragma unroll
    for (int i = 0; i < 8; ++i)
        #pragma unroll
        for (int jj = 0; jj < 4; ++jj) acc2[i][jj] = 0ull;

    for (int k0 = 0; k0 < H_DIM; k0 += 16) {
        float4 a0 = *(const float4*)(arow0 + k0);
        float4 a1 = *(const float4*)(arow1 + k0);
        float4 b0 = *(const float4*)(brow0 + k0);
        float4 b1 = *(const float4*)(brow1 + k0);
        __syncthreads();
        As[c4*4+0][r0]    = a0.x; As[c4*4+1][r0]    = a0.y;
        As[c4*4+2][r0]    = a0.z; As[c4*4+3][r0]    = a0.w;
        As[c4*4+0][r0+64] = a1.x; As[c4*4+1][r0+64] = a1.y;
        As[c4*4+2][r0+64] = a1.z; As[c4*4+3][r0+64] = a1.w;
        Bs[c4*4+0][r0]    = b0.x; Bs[c4*4+1][r0]    = b0.y;
        Bs[c4*4+2][r0]    = b0.z; Bs[c4*4+3][r0]    = b0.w;
        Bs[c4*4+0][r0+64] = b1.x; Bs[c4*4+1][r0+64] = b1.y;
        Bs[c4*4+2][r0+64] = b1.z; Bs[c4*4+3][r0+64] = b1.w;
        __syncthreads();
        #pragma unroll
        for (int k = 0; k < 16; ++k) {
            float a[8];
            *(float4*)(a + 0) = *(const float4*)&As[k][ty * 8];
            *(float4*)(a + 4) = *(const float4*)&As[k][ty * 8 + 4];
            // b pairs read as packed 64-bit lanes (16B-aligned: row = 528B)
            ulonglong2 bq0 = *(const ulonglong2*)&Bs[k][tx * 8];
            ulonglong2 bq1 = *(const ulonglong2*)&Bs[k][tx * 8 + 4];
            #pragma unroll
            for (int i = 0; i < 8; ++i) {
                unsigned long long pa = pack2(a[i], a[i]);
                ffma2(acc2[i][0], pa, bq0.x);
                ffma2(acc2[i][1], pa, bq0.y);
                ffma2(acc2[i][2], pa, bq1.x);
                ffma2(acc2[i][3], pa, bq1.y);
            }
        }
    }

    float bb[8];
    *(float4*)(bb + 0) = *(const float4*)(bias + n0 + tx * 8);
    *(float4*)(bb + 4) = *(const float4*)(bias + n0 + tx * 8 + 4);
    #pragma unroll
    for (int i = 0; i < 8; ++i) {
        float c[8];
        #pragma unroll
        for (int jj = 0; jj < 4; ++jj) unpack2(acc2[i][jj], c[2*jj], c[2*jj+1]);
        float* crow = g_xproj + (size_t)(m0 + ty * 8 + i) * NCOL + n0 + tx * 8;
        float4 v0 = make_float4(c[0] + bb[0], c[1] + bb[1], c[2] + bb[2], c[3] + bb[3]);
        float4 v1 = make_float4(c[4] + bb[4], c[5] + bb[5], c[6] + bb[6], c[7] + bb[7]);
        *(float4*)(crow)     = v0;
        *(float4*)(crow + 4) = v1;
    }
}

// ---------------------------------------------------------------------------
// Kernel 2: persistent GRU scan. EXACT round-2 sync protocol (flags + fence,
// the only scheme with a passing run). Only the dot-product arithmetic is
// changed to packed FFMA2.
// ---------------------------------------------------------------------------
__global__ void __launch_bounds__(512, 1) gru_scan_kernel(
    const float* __restrict__ w_hh,   // (6144, 1024)
    const float* __restrict__ b_hh,   // (6144)
    float* __restrict__ out)          // (T, 2048) then hidden row
{
    __shared__ float hsm[H_DIM];
    __shared__ float hnew_sm[16];

    const int tid   = threadIdx.x;
    const int lane  = tid & 31;
    const int wrp   = tid >> 5;            // 0..15
    const int blk   = blockIdx.x;          // 0..127
    const int d     = blk >> 6;            // 0 or 1
    const int jbase = (blk & 63) * 16;
    const int j     = jbase + wrp;         // unit 0..1023

    const size_t rr = (size_t)(d * 3072 + j) * H_DIM;
    const size_t rz = rr + (size_t)1024 * H_DIM;
    const size_t rn = rz + (size_t)1024 * H_DIM;

    // Weight preload as packed pairs: lane covers h = i*128 + lane*4 + {0..3}
    unsigned long long wr2[16], wz2[16], wn2[16];
    {
        const ulonglong2* pr = (const ulonglong2*)(w_hh + rr);
        const ulonglong2* pz = (const ulonglong2*)(w_hh + rz);
        const ulonglong2* pn = (const ulonglong2*)(w_hh + rn);
        #pragma unroll
        for (int i = 0; i < 8; ++i) {
            ulonglong2 a = pr[i * 32 + lane]; wr2[2*i] = a.x; wr2[2*i+1] = a.y;
            ulonglong2 b = pz[i * 32 + lane]; wz2[2*i] = b.x; wz2[2*i+1] = b.y;
            ulonglong2 c = pn[i * 32 + lane]; wn2[2*i] = c.x; wn2[2*i+1] = c.y;
        }
    }
    float bhr = 0.f, bhz = 0.f, bhn = 0.f;
    if (lane == 0) {
        bhr = __ldg(b_hh + d * 3072 + j);
        bhz = __ldg(b_hh + d * 3072 + 1024 + j);
        bhn = __ldg(b_hh + d * 3072 + 2048 + j);
    }

    const float* xp = g_xproj + d * 3072 + j;

    for (int s = 0; s < T_LEN; ++s) {
        // Prefetch x-gate inputs (independent of h; hides DRAM latency)
        float xr = 0.f, xz = 0.f, xn = 0.f;
        if (lane == 0) {
            const float* p = xp + (size_t)s * NCOL;
            xr = __ldg(p);
            xz = __ldg(p + 1024);
            xn = __ldg(p + 2048);
        }

        // Wait until all producers of this direction finished step s-1
        if (tid < 64) {
            volatile int* f = g_flags + (d << 6) + tid;
            while (*f < s) { }
        }
        __syncthreads();

        // Stage h_s into smem (L2-coherent loads; L1 may be stale cross-SM)
        if (tid < 256) {
            const float4* hb = (const float4*)(&g_h[s & 1][d][0]);
            ((float4*)hsm)[tid] = __ldcg(hb + tid);
        }
        __syncthreads();

        // 3 dot products of length 1024 via packed FFMA2 (48 per thread)
        unsigned long long ar2 = 0ull, az2 = 0ull, an2 = 0ull;
        #pragma unroll
        for (int i = 0; i < 8; ++i) {
            ulonglong2 hv = ((const ulonglong2*)hsm)[i * 32 + lane];
            ffma2(ar2, wr2[2*i],   hv.x);
            ffma2(ar2, wr2[2*i+1], hv.y);
            ffma2(az2, wz2[2*i],   hv.x);
            ffma2(az2, wz2[2*i+1], hv.y);
            ffma2(an2, wn2[2*i],   hv.x);
            ffma2(an2, wn2[2*i+1], hv.y);
        }
        float lo, hi, ar, az, an;
        unpack2(ar2, lo, hi); ar = lo + hi;
        unpack2(az2, lo, hi); az = lo + hi;
        unpack2(an2, lo, hi); an = lo + hi;
        #pragma unroll
        for (int o = 16; o > 0; o >>= 1) {
            ar += __shfl_xor_sync(0xffffffffu, ar, o);
            az += __shfl_xor_sync(0xffffffffu, az, o);
            an += __shfl_xor_sync(0xffffffffu, an, o);
        }

        if (lane == 0) {
            float r = 1.f / (1.f + __expf(-(xr + ar + bhr)));
            float z = 1.f / (1.f + __expf(-(xz + az + bhz)));
            float n = tanhf(xn + r * (an + bhn));
            float hprev = hsm[j];
            hnew_sm[wrp] = (1.f - z) * n + z * hprev;
        }
        __syncthreads();

        // Publish: outputs row + next-step h slice + release flag (round-2 exact)
        if (tid < 16)
            out[(size_t)s * 2048 + d * 1024 + jbase + tid] = hnew_sm[tid];
        if (tid == 0) {
            float4*       dst = (float4*)(&g_h[(s + 1) & 1][d][jbase]);
            const float4* src = (const float4*)hnew_sm;
            dst[0] = src[0]; dst[1] = src[1]; dst[2] = src[2]; dst[3] = src[3];
            __threadfence();
            ((volatile int*)g_flags)[blk] = s + 1;
        }
    }
}

// ---------------------------------------------------------------------------
// Kernel 3: hidden = h_T[dir0] + h_T[dir1]  (final state lives in buffer 0)
// ---------------------------------------------------------------------------
__global__ void hidden_kernel(float* __restrict__ out)
{
    int j = threadIdx.x;
    out[(size_t)T_LEN * 2048 + j] = g_h[0][0][j] + g_h[0][1][j];
}

// ---------------------------------------------------------------------------
extern "C" void kernel_launch(void* const* d_in, const int* in_sizes, int n_in,
                              void* d_out, int out_size)
{
    const int*   x    = (const int*)d_in[0];
    const float* emb  = (const float*)d_in[1];
    const float* w_ih = (const float*)d_in[2];
    const float* w_hh = (const float*)d_in[3];
    const float* b_ih = (const float*)d_in[4];
    const float* b_hh = (const float*)d_in[5];
    float* out = (float*)d_out;

    void* pflags = nullptr;
    void* ph     = nullptr;
    cudaGetSymbolAddress(&pflags, g_flags);
    cudaGetSymbolAddress(&ph,     g_h);
    cudaMemsetAsync(pflags, 0, sizeof(int) * 128, 0);
    cudaMemsetAsync(ph,     0, sizeof(float) * 2 * 2 * H_DIM, 0);

    gemm_xproj_kernel<<<dim3(NCOL / 128, T_LEN / 128), 256>>>(x, emb, w_ih, b_ih);
    gru_scan_kernel<<<128, 512>>>(w_hh, b_hh, out);
    hidden_kernel<<<1, H_DIM>>>(out);
}